// round 1
// baseline (speedup 1.0000x reference)
#include <cuda_runtime.h>

#define NTOK 65536
#define KCB  8192
#define DDIM 64
#define DECAYF 0.9f
#define EPSF 1e-5f

// ---- scratch (no allocation allowed) ----
__device__ float g_cnorm[KCB];
__device__ int   g_token[NTOK];
__device__ float g_counts[KCB];
__device__ float g_embed_sum[KCB * DDIM];
__device__ float g_qerr;
__device__ float g_nsum;

// ---------------- zero scratch ----------------
__global__ void k_zero() {
    int i = blockIdx.x * blockDim.x + threadIdx.x;
    if (i < KCB * DDIM) g_embed_sum[i] = 0.0f;
    if (i < KCB)        g_counts[i]    = 0.0f;
    if (i == 0) { g_qerr = 0.0f; g_nsum = 0.0f; }
}

// ---------------- codebook norms: warp per code ----------------
__global__ void k_cnorm(const float* __restrict__ w) {
    int warp = (blockIdx.x * blockDim.x + threadIdx.x) >> 5;
    int lane = threadIdx.x & 31;
    if (warp >= KCB) return;
    float v0 = w[warp * DDIM + lane];
    float v1 = w[warp * DDIM + 32 + lane];
    float s = v0 * v0 + v1 * v1;
    #pragma unroll
    for (int o = 16; o; o >>= 1) s += __shfl_xor_sync(0xffffffffu, s, o);
    if (lane == 0) g_cnorm[warp] = s;
}

// ---------------- fused GEMM + argmin ----------------
// Block: 64 tokens x full K. Chunk: 128 codes.
// 128 threads: tx = tid&7 -> 8 token-groups of 8 tokens (4 f32x2 pairs),
//              ty = tid>>3 -> 16 code-groups of 8 codes.
static constexpr int BT  = 64;
static constexpr int CC  = 128;
static constexpr int TPB = 128;
static constexpr int SMEM_MAIN = DDIM * BT * 4 + DDIM * CC * 8 + CC * 4; // 82432

__device__ __forceinline__ unsigned long long ffma2(
    unsigned long long a, unsigned long long b, unsigned long long c) {
    unsigned long long d;
    asm("fma.rn.f32x2 %0, %1, %2, %3;" : "=l"(d) : "l"(a), "l"(b), "l"(c));
    return d;
}

__global__ __launch_bounds__(TPB) void k_main(const float* __restrict__ z,
                                              const float* __restrict__ w) {
    extern __shared__ float smem[];
    float* zs = smem;                                                    // [64][BT]
    unsigned long long* wsd = (unsigned long long*)(smem + DDIM * BT);   // [64][CC] (w,w) pairs
    float* cns = (float*)(wsd + DDIM * CC);                              // [CC]

    const int tid  = threadIdx.x;
    const int tx   = tid & 7;
    const int ty   = tid >> 3;
    const int tok0 = blockIdx.x * BT;

    // Load z tile transposed: zs[d][t]
    for (int i = tid; i < BT * DDIM; i += TPB) {
        int t = i >> 6, d = i & 63;
        zs[d * BT + t] = z[(size_t)(tok0 + t) * DDIM + d];
    }

    float bestv[8];
    int   besti[8];
    #pragma unroll
    for (int t = 0; t < 8; t++) { bestv[t] = 3.4e38f; besti[t] = 0; }

    for (int cb = 0; cb < KCB; cb += CC) {
        __syncthreads();
        // Load w chunk, duplicated into f32x2 pairs: wsd[d][c] = (w, w)
        for (int i = tid; i < CC * DDIM; i += TPB) {
            int c = i >> 6, d = i & 63;
            unsigned int u = __float_as_uint(w[(size_t)(cb + c) * DDIM + d]);
            wsd[d * CC + c] = ((unsigned long long)u << 32) | (unsigned long long)u;
        }
        if (tid < CC) cns[tid] = g_cnorm[cb + tid];
        __syncthreads();

        unsigned long long acc[4][8];
        #pragma unroll
        for (int i = 0; i < 4; i++)
            #pragma unroll
            for (int j = 0; j < 8; j++) acc[i][j] = 0ull;

        const float* zrow = zs + tx * 8;
        const unsigned long long* wrow = wsd + ty * 8;

        #pragma unroll 8
        for (int d = 0; d < DDIM; d++) {
            ulonglong2 za = *(const ulonglong2*)(zrow + (size_t)d * BT);
            ulonglong2 zb = *(const ulonglong2*)(zrow + (size_t)d * BT + 4);
            ulonglong2 w0 = *(const ulonglong2*)(wrow + (size_t)d * CC);
            ulonglong2 w1 = *(const ulonglong2*)(wrow + (size_t)d * CC + 2);
            ulonglong2 w2 = *(const ulonglong2*)(wrow + (size_t)d * CC + 4);
            ulonglong2 w3 = *(const ulonglong2*)(wrow + (size_t)d * CC + 6);
            unsigned long long zp[4] = {za.x, za.y, zb.x, zb.y};
            unsigned long long wp[8] = {w0.x, w0.y, w1.x, w1.y, w2.x, w2.y, w3.x, w3.y};
            #pragma unroll
            for (int i = 0; i < 4; i++)
                #pragma unroll
                for (int j = 0; j < 8; j++)
                    acc[i][j] = ffma2(zp[i], wp[j], acc[i][j]);
        }

        float cn[8];
        #pragma unroll
        for (int j = 0; j < 8; j++) cn[j] = cns[ty * 8 + j];

        // dist' = ||c||^2 - 2 z.c  (||z||^2 dropped: constant per token)
        #pragma unroll
        for (int i = 0; i < 4; i++) {
            #pragma unroll
            for (int j = 0; j < 8; j++) {
                float lo = __uint_as_float((unsigned int)(acc[i][j] & 0xffffffffu));
                float hi = __uint_as_float((unsigned int)(acc[i][j] >> 32));
                int ci = cb + ty * 8 + j;
                float d0 = fmaf(-2.0f, lo, cn[j]);
                float d1 = fmaf(-2.0f, hi, cn[j]);
                if (d0 < bestv[2 * i])     { bestv[2 * i]     = d0; besti[2 * i]     = ci; }
                if (d1 < bestv[2 * i + 1]) { bestv[2 * i + 1] = d1; besti[2 * i + 1] = ci; }
            }
        }
    }

    // Cross-thread (over ty) argmin reduce, first-min tie-break.
    __syncthreads();
    float* sval = smem;                      // [16][64]
    int*   sidx = (int*)(smem + 16 * 64);    // [16][64]
    #pragma unroll
    for (int t = 0; t < 8; t++) {
        sval[ty * 64 + tx * 8 + t] = bestv[t];
        sidx[ty * 64 + tx * 8 + t] = besti[t];
    }
    __syncthreads();
    if (tid < BT) {
        float bv = sval[tid];
        int   bi = sidx[tid];
        #pragma unroll
        for (int yy = 1; yy < 16; yy++) {
            float v = sval[yy * 64 + tid];
            int  ii = sidx[yy * 64 + tid];
            if (v < bv || (v == bv && ii < bi)) { bv = v; bi = ii; }
        }
        g_token[tok0 + tid] = bi;
    }
}

// ---------------- scatter: counts, embed_sum, quant error ----------------
__global__ void k_scatter(const float* __restrict__ z, const float* __restrict__ w) {
    __shared__ float qs[8];
    int warp = threadIdx.x >> 5;
    int lane = threadIdx.x & 31;
    int n = blockIdx.x * 8 + warp;
    int k = g_token[n];
    float z0 = z[(size_t)n * DDIM + lane];
    float z1 = z[(size_t)n * DDIM + 32 + lane];
    float w0 = w[(size_t)k * DDIM + lane];
    float w1 = w[(size_t)k * DDIM + 32 + lane];
    atomicAdd(&g_embed_sum[k * DDIM + lane], z0);
    atomicAdd(&g_embed_sum[k * DDIM + 32 + lane], z1);
    float d0 = w0 - z0, d1 = w1 - z1;
    float s = d0 * d0 + d1 * d1;
    #pragma unroll
    for (int o = 16; o; o >>= 1) s += __shfl_xor_sync(0xffffffffu, s, o);
    if (lane == 0) { qs[warp] = s; atomicAdd(&g_counts[k], 1.0f); }
    __syncthreads();
    if (threadIdx.x == 0) {
        float t = 0.0f;
        #pragma unroll
        for (int i = 0; i < 8; i++) t += qs[i];
        atomicAdd(&g_qerr, t);
    }
}

// ---------------- EMA stage 1: cluster size + n sum ----------------
__global__ void k_ema1(const float* __restrict__ cs, float* __restrict__ out) {
    __shared__ float red[256];
    int k = blockIdx.x * blockDim.x + threadIdx.x;
    float ncs = cs[k] * DECAYF + (1.0f - DECAYF) * g_counts[k];
    out[1 + KCB * DDIM + k] = ncs;
    red[threadIdx.x] = ncs;
    __syncthreads();
    for (int s = 128; s; s >>= 1) {
        if (threadIdx.x < s) red[threadIdx.x] += red[threadIdx.x + s];
        __syncthreads();
    }
    if (threadIdx.x == 0) atomicAdd(&g_nsum, red[0]);
}

// ---------------- EMA stage 2: embed_avg, weight refresh, qerr ----------------
__global__ void k_ema2(const float* __restrict__ ea, float* __restrict__ out) {
    int i = blockIdx.x * blockDim.x + threadIdx.x;
    if (i < KCB * DDIM) {
        float nea = ea[i] * DECAYF + (1.0f - DECAYF) * g_embed_sum[i];
        out[1 + KCB * DDIM + KCB + i] = nea;      // new_embed_avg
        int k = i >> 6;
        float ncs = out[1 + KCB * DDIM + k];
        float n = g_nsum;
        float smoothed = (ncs + EPSF) / (n + (float)KCB * EPSF) * n;
        out[1 + i] = nea / smoothed;              // new_weight
    }
    if (i == 0) out[0] = g_qerr / (float)NTOK;    // quant_error
}

extern "C" void kernel_launch(void* const* d_in, const int* in_sizes, int n_in,
                              void* d_out, int out_size) {
    const float* z  = (const float*)d_in[0];
    const float* w  = (const float*)d_in[1];
    const float* cs = (const float*)d_in[2];
    const float* ea = (const float*)d_in[3];
    float* out = (float*)d_out;

    cudaFuncSetAttribute(k_main, cudaFuncAttributeMaxDynamicSharedMemorySize, SMEM_MAIN);

    k_zero<<<(KCB * DDIM + 255) / 256, 256>>>();
    k_cnorm<<<KCB / 8, 256>>>(w);
    k_main<<<NTOK / BT, TPB, SMEM_MAIN>>>(z, w);
    k_scatter<<<NTOK / 8, 256>>>(z, w);
    k_ema1<<<KCB / 256, 256>>>(cs, out);
    k_ema2<<<(KCB * DDIM + 255) / 256, 256>>>(ea, out);
}